// round 8
// baseline (speedup 1.0000x reference)
#include <cuda_runtime.h>
#include <cuda_bf16.h>
#include <cuda_fp16.h>
#include <math.h>
#include <cstdint>

#define N_TOK 8192
#define F_DIM 256
#define OUTD  64
#define NSPLIT 2
#define JCHUNK (N_TOK / NSPLIT)   /* 4096 */
#define M_TILE 128
#define JT 64                     /* j per tile */
#define NT_PER_CTA (JCHUNK / JT)  /* 64 tiles */
#define LOG2E 1.4426950408889634f

/* ---------------- scratch (no allocation allowed) ---------------- */
__device__ __half g_ftsT[OUTD * N_TOK];            /* [c][j] transposed f16 */
__device__ float g_f1[N_TOK];
__device__ float g_f2[N_TOK];
__device__ float g_f2max;
__device__ float g_acc[NSPLIT * N_TOK * OUTD];     /* 4 MB */
__device__ float g_den[NSPLIT * N_TOK];

/* ---------------- helpers ---------------- */
__device__ __forceinline__ uint32_t smem_u32(const void* p) {
    uint32_t a;
    asm("{ .reg .u64 t; cvta.to.shared.u64 t, %1; cvt.u32.u64 %0, t; }" : "=r"(a) : "l"(p));
    return a;
}
/* pack two fp32 -> f16x2, memory order [a, b] */
__device__ __forceinline__ uint32_t cvt2h(float a, float b) {
    uint32_t r;
    asm("cvt.rn.f16x2.f32 %0, %1, %2;" : "=r"(r) : "f"(b), "f"(a));
    return r;
}
__device__ __forceinline__ uint32_t ex2h2(uint32_t x) {
    uint32_t r;
    asm("ex2.approx.f16x2 %0, %1;" : "=r"(r) : "r"(x));
    return r;
}
__device__ __forceinline__ void ldsm4(uint32_t& r0, uint32_t& r1, uint32_t& r2, uint32_t& r3,
                                      uint32_t addr) {
    asm volatile("ldmatrix.sync.aligned.m8n8.x4.shared.b16 {%0,%1,%2,%3}, [%4];"
                 : "=r"(r0), "=r"(r1), "=r"(r2), "=r"(r3) : "r"(addr));
}
__device__ __forceinline__ void mma16816(float* d, const uint32_t* a, uint32_t b0, uint32_t b1) {
    asm volatile("mma.sync.aligned.m16n8k16.row.col.f32.f16.f16.f32 "
                 "{%0,%1,%2,%3},{%4,%5,%6,%7},{%8,%9},{%0,%1,%2,%3};"
                 : "+f"(d[0]), "+f"(d[1]), "+f"(d[2]), "+f"(d[3])
                 : "r"(a[0]), "r"(a[1]), "r"(a[2]), "r"(a[3]), "r"(b0), "r"(b1));
}
/* full/empty barriers span producers+consumers = 768 threads */
#define BAR_SYNC768(id)   asm volatile("bar.sync %0, 768;"   :: "r"(id) : "memory")
#define BAR_ARRIVE768(id) asm volatile("bar.arrive %0, 768;" :: "r"(id) : "memory")
/* intra-role barriers */
#define BAR_SYNC512(id)   asm volatile("bar.sync %0, 512;"   :: "r"(id) : "memory")
#define BAR_SYNC256(id)   asm volatile("bar.sync %0, 256;"   :: "r"(id) : "memory")
#define CP_ASYNC16(dst, src) \
    asm volatile("cp.async.cg.shared.global [%0], [%1], 16;" :: "r"(dst), "l"(src) : "memory")
#define CP_COMMIT() asm volatile("cp.async.commit_group;" ::: "memory")
#define CP_WAIT2()  asm volatile("cp.async.wait_group 2;" ::: "memory")

/* ------------------------------------------------------------------ */
/* k1: seq_fts = seq @ W1 -> transposed f16 ; f1, f2                   */
/* ------------------------------------------------------------------ */
__global__ __launch_bounds__(256) void k1_fts(const float* __restrict__ seq,
        const float* __restrict__ W1, const float* __restrict__ a1,
        const float* __restrict__ b1, const float* __restrict__ a2,
        const float* __restrict__ b2) {
    __shared__ float As[64 * 68];
    __shared__ float Bs[64 * 64];
    __shared__ float a1s[OUTD], a2s[OUTD];

    const int tid = threadIdx.x;
    const int rb  = blockIdx.x * 64;
    if (tid < OUTD) { a1s[tid] = a1[tid]; a2s[tid] = a2[tid]; }

    const int cg = tid & 15, rg = tid >> 4;
    const int r0 = rg * 4,  c0 = cg * 4;

    float acc[4][4];
#pragma unroll
    for (int i = 0; i < 4; ++i)
#pragma unroll
        for (int j = 0; j < 4; ++j) acc[i][j] = 0.f;

    const float4* seq4 = (const float4*)seq;
    const float4* W14  = (const float4*)W1;
    float4* As4 = (float4*)As;
    float4* Bs4 = (float4*)Bs;

    for (int kb = 0; kb < 4; ++kb) {
        __syncthreads();
#pragma unroll
        for (int t = tid; t < 1024; t += 256) {
            const int r = t >> 4, c4 = t & 15;
            As4[r * 17 + c4] = seq4[(rb + r) * 64 + kb * 16 + c4];
            Bs4[t]           = W14[(kb * 64 + r) * 16 + c4];
        }
        __syncthreads();
#pragma unroll
        for (int k = 0; k < 64; ++k) {
            const float4 b = Bs4[k * 16 + cg];
#pragma unroll
            for (int ri = 0; ri < 4; ++ri) {
                const float a = As[(r0 + ri) * 68 + k];
                acc[ri][0] += a * b.x; acc[ri][1] += a * b.y;
                acc[ri][2] += a * b.z; acc[ri][3] += a * b.w;
            }
        }
    }

    /* write transposed f16: g_ftsT[c][row] */
#pragma unroll
    for (int ci = 0; ci < 4; ++ci) {
        const int c = c0 + ci;
        *(uint2*)(g_ftsT + (size_t)c * N_TOK + rb + r0) =
            make_uint2(cvt2h(acc[0][ci], acc[1][ci]), cvt2h(acc[2][ci], acc[3][ci]));
    }

    /* f1 / f2 */
#pragma unroll
    for (int ri = 0; ri < 4; ++ri) {
        float p1 = acc[ri][0] * a1s[c0] + acc[ri][1] * a1s[c0 + 1]
                 + acc[ri][2] * a1s[c0 + 2] + acc[ri][3] * a1s[c0 + 3];
        float p2 = acc[ri][0] * a2s[c0] + acc[ri][1] * a2s[c0 + 1]
                 + acc[ri][2] * a2s[c0 + 2] + acc[ri][3] * a2s[c0 + 3];
#pragma unroll
        for (int off = 8; off > 0; off >>= 1) {
            p1 += __shfl_xor_sync(0xffffffffu, p1, off);
            p2 += __shfl_xor_sync(0xffffffffu, p2, off);
        }
        if (cg == 0) {
            g_f1[rb + r0 + ri] = p1 + b1[0];
            g_f2[rb + r0 + ri] = p2 + b2[0];
        }
    }
}

/* ------------------------------------------------------------------ */
__global__ void k2_max() {
    __shared__ float red[256];
    const int tid = threadIdx.x;
    float m = -1e30f;
    for (int i = tid; i < N_TOK; i += 256) m = fmaxf(m, g_f2[i]);
    red[tid] = m; __syncthreads();
    for (int s = 128; s > 0; s >>= 1) {
        if (tid < s) red[tid] = fmaxf(red[tid], red[tid + s]);
        __syncthreads();
    }
    if (tid == 0) g_f2max = red[0];
}

/* ------------------------------------------------------------------ */
/* k3: 768 threads: warps 0-15 produce P (bias ring + ex2.f16x2),      */
/* warps 16-23 consume (ldmatrix + f16 HMMA). Denominator via ones-col */
/* ------------------------------------------------------------------ */
#define PSTRB 144                 /* bytes per smem tile row (72 f16) */
#define PH_OFF 0                  /* 2 stages x 128*144 = 36864 */
#define VH_OFF 36864              /* 80 rows x 144 = 11520 (64 V + 16 ones) */
#define FCL_OFF 48384             /* 128 x float2 = 1024 */
#define BIAS_OFF 49408            /* 4 stages x 32768 */
#define BIAS_STG 32768
#define SMEM3_BYTES (BIAS_OFF + 4 * BIAS_STG)   /* 180480 */

__global__ __launch_bounds__(768, 1) void k3_attn(const float* __restrict__ bias) {
    extern __shared__ char sm[];
    const uint32_t sbase = smem_u32(sm);
    float2* fcl = (float2*)(sm + FCL_OFF);        /* {f1, -m*log2e} per row */

    const int tid  = threadIdx.x;
    const int wid  = tid >> 5, lane = tid & 31;
    const int ibase = blockIdx.x * M_TILE;
    const int s     = blockIdx.y;
    const int jbase0 = s * JCHUNK;

    if (tid < M_TILE) {
        const float f1v = g_f1[ibase + tid];
        const float x = f1v + g_f2max;
        fcl[tid] = make_float2(f1v, -fmaxf(x, 0.2f * x) * LOG2E);
    }
    __syncthreads();

    if (wid < 16) {
        /* ===================== PRODUCERS (512 thr) ===================== */
        const int jq    = lane & 15;
        const int rgrp  = wid * 2 + (lane >> 4);     /* 0..31 */

        /* prologue: prefetch bias tiles 0,1,2 */
#pragma unroll
        for (int pt = 0; pt < 3; ++pt) {
            const int jb2 = jbase0 + pt * JT;
            const uint32_t dbase = sbase + BIAS_OFF + pt * BIAS_STG;
#pragma unroll
            for (int q = 0; q < 4; ++q) {
                const int u = q * 512 + tid;
                const int row = u >> 4, c4 = u & 15;
                CP_ASYNC16(dbase + row * 256 + c4 * 16,
                           bias + (size_t)(ibase + row) * N_TOK + jb2 + c4 * 4);
            }
            CP_COMMIT();
        }

        for (int t = 0; t < NT_PER_CTA; ++t) {
            const int st = t & 1;
            const int jb = jbase0 + t * JT;
            if (t >= 2) BAR_SYNC768(3 + st);         /* P buffer empty */

            CP_WAIT2();                               /* bias tile t landed (mine) */
            BAR_SYNC512(5);                           /* all producers synced */

            /* prefetch bias tile t+3 */
            if (t + 3 < NT_PER_CTA) {
                const int slot = (t + 3) & 3;
                const int jb2 = jbase0 + (t + 3) * JT;
                const uint32_t dbase = sbase + BIAS_OFF + slot * BIAS_STG;
#pragma unroll
                for (int q = 0; q < 4; ++q) {
                    const int u = q * 512 + tid;
                    const int row = u >> 4, c4 = u & 15;
                    CP_ASYNC16(dbase + row * 256 + c4 * 16,
                               bias + (size_t)(ibase + row) * N_TOK + jb2 + c4 * 4);
                }
            }
            CP_COMMIT();

            /* generate P tile: 128 rows x 64 j -> f16 via ex2.f16x2 */
            char* ph = sm + PH_OFF + st * 18432;
            const char* bslot = sm + BIAS_OFF + (t & 3) * BIAS_STG;
            const float4 f2v = *((const float4*)(g_f2 + jb) + jq);
#pragma unroll
            for (int k = 0; k < 4; ++k) {
                const int i = rgrp + k * 32;
                const float2 fc = fcl[i];
                const float4 bv = *(const float4*)(bslot + i * 256 + jq * 16);
                float x, t0, t1, t2, t3;
                x = fc.x + f2v.x; t0 = fmaxf(x, 0.2f * x);
                x = fc.x + f2v.y; t1 = fmaxf(x, 0.2f * x);
                x = fc.x + f2v.z; t2 = fmaxf(x, 0.2f * x);
                x = fc.x + f2v.w; t3 = fmaxf(x, 0.2f * x);
                const float g0 = fmaf(t0, LOG2E, fmaf(bv.x, LOG2E, fc.y));
                const float g1 = fmaf(t1, LOG2E, fmaf(bv.y, LOG2E, fc.y));
                const float g2 = fmaf(t2, LOG2E, fmaf(bv.z, LOG2E, fc.y));
                const float g3 = fmaf(t3, LOG2E, fmaf(bv.w, LOG2E, fc.y));
                *(uint2*)(ph + i * PSTRB + jq * 8) =
                    make_uint2(ex2h2(cvt2h(g0, g1)), ex2h2(cvt2h(g2, g3)));
            }
            BAR_ARRIVE768(1 + st);                   /* signal P full */
        }
    } else {
        /* ===================== CONSUMERS (256 thr) ===================== */
        const int cw   = wid - 16;                   /* 0..7, 16 rows each */
        const int ctid = tid - 512;                  /* 0..255 */
        float acc[9][4];
#pragma unroll
        for (int n = 0; n < 9; ++n)
#pragma unroll
            for (int q = 0; q < 4; ++q) acc[n][q] = 0.f;

        const uint32_t rsel = (uint32_t)(lane & 15) * PSTRB + (uint32_t)(lane >> 4) * 16;
        const uint32_t vhb = sbase + VH_OFF;

        /* init ones block: V rows 64..79 (col 64 = 1.0, cols 65..79 = 0) */
        for (int u = ctid; u < 16 * 36; u += 256) {
            const int r = u / 36, w = u % 36;
            ((uint32_t*)(sm + VH_OFF + (64 + r) * PSTRB))[w] = (r == 0) ? 0x3C003C00u : 0u;
        }

        for (int t = 0; t < NT_PER_CTA; ++t) {
            const int st = t & 1;
            const int jb = jbase0 + t * JT;

            /* issue V loads early (latency hides under the full-wait) */
            uint4 vh_r[2];
#pragma unroll
            for (int r = 0; r < 2; ++r) {
                const int u = r * 256 + ctid;
                const int c = u >> 3, q = u & 7;
                vh_r[r] = *((const uint4*)(g_ftsT + (size_t)c * N_TOK + jb) + q);
            }

            BAR_SYNC768(1 + st);                     /* P full */

            /* stage V into (single) smem buffer */
#pragma unroll
            for (int r = 0; r < 2; ++r) {
                const int u = r * 256 + ctid;
                const int c = u >> 3, q = u & 7;
                *(uint4*)(sm + VH_OFF + c * PSTRB + q * 16) = vh_r[r];
            }
            BAR_SYNC256(7);                          /* V (+ones) visible */

            const uint32_t ph = sbase + PH_OFF + st * 18432;

#pragma unroll
            for (int ks = 0; ks < 4; ++ks) {
                const uint32_t kofs = (uint32_t)ks * 32;   /* 16 f16 = 32B */
                uint32_t ah[4];
                ldsm4(ah[0], ah[1], ah[2], ah[3],
                      ph + (cw * 16) * PSTRB + kofs + rsel);
#pragma unroll
                for (int np = 0; np < 4; ++np) {
                    uint32_t bh[4];
                    ldsm4(bh[0], bh[1], bh[2], bh[3],
                          vhb + (np * 16) * PSTRB + kofs + rsel);
                    mma16816(acc[np * 2],     ah, bh[0], bh[2]);
                    mma16816(acc[np * 2 + 1], ah, bh[1], bh[3]);
                }
                /* ones block (rows 64..79): row-sum column */
                {
                    uint32_t bh[4];
                    ldsm4(bh[0], bh[1], bh[2], bh[3],
                          vhb + 64 * PSTRB + kofs + rsel);
                    mma16816(acc[8], ah, bh[0], bh[2]);
                }
            }
            BAR_ARRIVE768(3 + st);                   /* signal P empty */
        }

        /* write partials + denominators (rows cw*16 .. cw*16+15) */
        {
            const int m = cw * 16 + (lane >> 2);
            float* dst0 = g_acc + ((size_t)s * N_TOK + ibase + m) * OUTD;
            float* dst8 = dst0 + 8 * OUTD;
#pragma unroll
            for (int n = 0; n < 8; ++n) {
                const int c = n * 8 + (lane & 3) * 2;
                *(float2*)(dst0 + c) = make_float2(acc[n][0], acc[n][1]);
                *(float2*)(dst8 + c) = make_float2(acc[n][2], acc[n][3]);
            }
            if ((lane & 3) == 0) {
                g_den[(size_t)s * N_TOK + ibase + m]     = acc[8][0];
                g_den[(size_t)s * N_TOK + ibase + m + 8] = acc[8][2];
            }
        }
    }
}

/* ------------------------------------------------------------------ */
__global__ __launch_bounds__(256) void k4_combine(float* __restrict__ out) {
    const int idx = blockIdx.x * 256 + threadIdx.x;
    if (idx >= N_TOK * 16) return;
    const int i = idx >> 4;
    float den = 0.f;
    float4 a = make_float4(0.f, 0.f, 0.f, 0.f);
#pragma unroll
    for (int s = 0; s < NSPLIT; ++s) {
        den += g_den[s * N_TOK + i];
        const float4 p = ((const float4*)g_acc)[(size_t)s * N_TOK * 16 + idx];
        a.x += p.x; a.y += p.y; a.z += p.z; a.w += p.w;
    }
    const float inv = 1.f / den;
    float4 r = make_float4(a.x * inv, a.y * inv, a.z * inv, a.w * inv);
    r.x = r.x > 0.f ? r.x : expm1f(r.x);
    r.y = r.y > 0.f ? r.y : expm1f(r.y);
    r.z = r.z > 0.f ? r.z : expm1f(r.z);
    r.w = r.w > 0.f ? r.w : expm1f(r.w);
    ((float4*)out)[idx] = r;
}

/* ------------------------------------------------------------------ */
extern "C" void kernel_launch(void* const* d_in, const int* in_sizes, int n_in,
                              void* d_out, int out_size) {
    const float* seq  = (const float*)d_in[0];
    const float* bias = (const float*)d_in[1];
    const float* W1   = (const float*)d_in[2];
    const float* a1   = (const float*)d_in[3];
    const float* b1   = (const float*)d_in[4];
    const float* a2   = (const float*)d_in[5];
    const float* b2   = (const float*)d_in[6];
    float* out = (float*)d_out;

    cudaFuncSetAttribute(k3_attn, cudaFuncAttributeMaxDynamicSharedMemorySize, SMEM3_BYTES);

    k1_fts<<<128, 256>>>(seq, W1, a1, b1, a2, b2);
    k2_max<<<1, 256>>>();
    dim3 g3(N_TOK / M_TILE, NSPLIT);
    k3_attn<<<g3, 768, SMEM3_BYTES>>>(bias);
    k4_combine<<<(N_TOK * 16) / 256, 256>>>(out);
}

// round 9
// speedup vs baseline: 1.0338x; 1.0338x over previous
#include <cuda_runtime.h>
#include <cuda_bf16.h>
#include <cuda_fp16.h>
#include <math.h>
#include <cstdint>

#define N_TOK 8192
#define F_DIM 256
#define OUTD  64
#define NSPLIT 2
#define JCHUNK (N_TOK / NSPLIT)   /* 4096 */
#define M_TILE 128
#define JT 64                     /* j per tile */
#define NT_PER_CTA (JCHUNK / JT)  /* 64 tiles */
#define LOG2E 1.4426950408889634f

/* ---------------- scratch (no allocation allowed) ---------------- */
__device__ __half g_ftsT[OUTD * N_TOK];            /* [c][j] transposed f16 */
__device__ float g_f1[N_TOK];
__device__ float g_f2[N_TOK];
__device__ float g_f2max;
__device__ float g_acc[NSPLIT * N_TOK * OUTD];     /* 4 MB */
__device__ float g_den[NSPLIT * N_TOK];

/* ---------------- helpers ---------------- */
__device__ __forceinline__ uint32_t smem_u32(const void* p) {
    uint32_t a;
    asm("{ .reg .u64 t; cvta.to.shared.u64 t, %1; cvt.u32.u64 %0, t; }" : "=r"(a) : "l"(p));
    return a;
}
/* pack two fp32 -> f16x2, memory order [a, b] */
__device__ __forceinline__ uint32_t cvt2h(float a, float b) {
    uint32_t r;
    asm("cvt.rn.f16x2.f32 %0, %1, %2;" : "=r"(r) : "f"(b), "f"(a));
    return r;
}
__device__ __forceinline__ uint32_t ex2h2(uint32_t x) {
    uint32_t r;
    asm("ex2.approx.f16x2 %0, %1;" : "=r"(r) : "r"(x));
    return r;
}
__device__ __forceinline__ void ldsm4(uint32_t& r0, uint32_t& r1, uint32_t& r2, uint32_t& r3,
                                      uint32_t addr) {
    asm volatile("ldmatrix.sync.aligned.m8n8.x4.shared.b16 {%0,%1,%2,%3}, [%4];"
                 : "=r"(r0), "=r"(r1), "=r"(r2), "=r"(r3) : "r"(addr));
}
__device__ __forceinline__ void mma16816(float* d, const uint32_t* a, uint32_t b0, uint32_t b1) {
    asm volatile("mma.sync.aligned.m16n8k16.row.col.f32.f16.f16.f32 "
                 "{%0,%1,%2,%3},{%4,%5,%6,%7},{%8,%9},{%0,%1,%2,%3};"
                 : "+f"(d[0]), "+f"(d[1]), "+f"(d[2]), "+f"(d[3])
                 : "r"(a[0]), "r"(a[1]), "r"(a[2]), "r"(a[3]), "r"(b0), "r"(b1));
}
/* full/empty barriers span producers+consumers = 512 threads */
#define BAR_SYNC512(id)   asm volatile("bar.sync %0, 512;"   :: "r"(id) : "memory")
#define BAR_ARRIVE512(id) asm volatile("bar.arrive %0, 512;" :: "r"(id) : "memory")
/* intra-role barriers: 256 threads */
#define BAR_SYNC256(id)   asm volatile("bar.sync %0, 256;"   :: "r"(id) : "memory")
#define CP_ASYNC16(dst, src) \
    asm volatile("cp.async.cg.shared.global [%0], [%1], 16;" :: "r"(dst), "l"(src) : "memory")
#define CP_COMMIT() asm volatile("cp.async.commit_group;" ::: "memory")
#define CP_WAIT2()  asm volatile("cp.async.wait_group 2;" ::: "memory")

/* ------------------------------------------------------------------ */
/* k1: seq_fts = seq @ W1 -> transposed f16 ; f1, f2                   */
/* ------------------------------------------------------------------ */
__global__ __launch_bounds__(256) void k1_fts(const float* __restrict__ seq,
        const float* __restrict__ W1, const float* __restrict__ a1,
        const float* __restrict__ b1, const float* __restrict__ a2,
        const float* __restrict__ b2) {
    __shared__ float As[64 * 68];
    __shared__ float Bs[64 * 64];
    __shared__ float a1s[OUTD], a2s[OUTD];

    const int tid = threadIdx.x;
    const int rb  = blockIdx.x * 64;
    if (tid < OUTD) { a1s[tid] = a1[tid]; a2s[tid] = a2[tid]; }

    const int cg = tid & 15, rg = tid >> 4;
    const int r0 = rg * 4,  c0 = cg * 4;

    float acc[4][4];
#pragma unroll
    for (int i = 0; i < 4; ++i)
#pragma unroll
        for (int j = 0; j < 4; ++j) acc[i][j] = 0.f;

    const float4* seq4 = (const float4*)seq;
    const float4* W14  = (const float4*)W1;
    float4* As4 = (float4*)As;
    float4* Bs4 = (float4*)Bs;

    for (int kb = 0; kb < 4; ++kb) {
        __syncthreads();
#pragma unroll
        for (int t = tid; t < 1024; t += 256) {
            const int r = t >> 4, c4 = t & 15;
            As4[r * 17 + c4] = seq4[(rb + r) * 64 + kb * 16 + c4];
            Bs4[t]           = W14[(kb * 64 + r) * 16 + c4];
        }
        __syncthreads();
#pragma unroll
        for (int k = 0; k < 64; ++k) {
            const float4 b = Bs4[k * 16 + cg];
#pragma unroll
            for (int ri = 0; ri < 4; ++ri) {
                const float a = As[(r0 + ri) * 68 + k];
                acc[ri][0] += a * b.x; acc[ri][1] += a * b.y;
                acc[ri][2] += a * b.z; acc[ri][3] += a * b.w;
            }
        }
    }

    /* write transposed f16: g_ftsT[c][row] */
#pragma unroll
    for (int ci = 0; ci < 4; ++ci) {
        const int c = c0 + ci;
        *(uint2*)(g_ftsT + (size_t)c * N_TOK + rb + r0) =
            make_uint2(cvt2h(acc[0][ci], acc[1][ci]), cvt2h(acc[2][ci], acc[3][ci]));
    }

    /* f1 / f2 */
#pragma unroll
    for (int ri = 0; ri < 4; ++ri) {
        float p1 = acc[ri][0] * a1s[c0] + acc[ri][1] * a1s[c0 + 1]
                 + acc[ri][2] * a1s[c0 + 2] + acc[ri][3] * a1s[c0 + 3];
        float p2 = acc[ri][0] * a2s[c0] + acc[ri][1] * a2s[c0 + 1]
                 + acc[ri][2] * a2s[c0 + 2] + acc[ri][3] * a2s[c0 + 3];
#pragma unroll
        for (int off = 8; off > 0; off >>= 1) {
            p1 += __shfl_xor_sync(0xffffffffu, p1, off);
            p2 += __shfl_xor_sync(0xffffffffu, p2, off);
        }
        if (cg == 0) {
            g_f1[rb + r0 + ri] = p1 + b1[0];
            g_f2[rb + r0 + ri] = p2 + b2[0];
        }
    }
}

/* ------------------------------------------------------------------ */
__global__ void k2_max() {
    __shared__ float red[256];
    const int tid = threadIdx.x;
    float m = -1e30f;
    for (int i = tid; i < N_TOK; i += 256) m = fmaxf(m, g_f2[i]);
    red[tid] = m; __syncthreads();
    for (int s = 128; s > 0; s >>= 1) {
        if (tid < s) red[tid] = fmaxf(red[tid], red[tid + s]);
        __syncthreads();
    }
    if (tid == 0) g_f2max = red[0];
}

/* ------------------------------------------------------------------ */
/* k3: 512 threads: warps 0-7 produce P (bias ring + ex2.f16x2),       */
/* warps 8-15 consume with 4x2 row/col split (min smem replication).   */
/* 3-stage P ring. Denominator via ones-col MMA (col-group 1 only).    */
/* ------------------------------------------------------------------ */
#define PSTRB 144                 /* bytes per smem tile row (72 f16) */
#define PSTG  18432               /* 128*144 */
#define PH_OFF 0                  /* 3 stages */
#define VH_OFF (3 * PSTG)         /* 55296: 80 rows x 144 = 11520 */
#define FCL_OFF 66816             /* 128 x float2 = 1024 */
#define BIAS_OFF 67840            /* 4 stages x 32768 */
#define BIAS_STG 32768
#define SMEM3_BYTES (BIAS_OFF + 4 * BIAS_STG)   /* 198912 */

__global__ __launch_bounds__(512, 1) void k3_attn(const float* __restrict__ bias) {
    extern __shared__ char sm[];
    const uint32_t sbase = smem_u32(sm);
    float2* fcl = (float2*)(sm + FCL_OFF);        /* {f1, -m*log2e} per row */

    const int tid  = threadIdx.x;
    const int wid  = tid >> 5, lane = tid & 31;
    const int ibase = blockIdx.x * M_TILE;
    const int s     = blockIdx.y;
    const int jbase0 = s * JCHUNK;

    if (tid < M_TILE) {
        const float f1v = g_f1[ibase + tid];
        const float x = f1v + g_f2max;
        fcl[tid] = make_float2(f1v, -fmaxf(x, 0.2f * x) * LOG2E);
    }
    __syncthreads();

    if (wid < 8) {
        /* ===================== PRODUCERS (256 thr) ===================== */
        const int jq    = lane & 15;
        const int rgrp  = wid * 2 + (lane >> 4);     /* 0..15 */

        /* prologue: prefetch bias tiles 0,1,2 */
#pragma unroll
        for (int pt = 0; pt < 3; ++pt) {
            const int jb2 = jbase0 + pt * JT;
            const uint32_t dbase = sbase + BIAS_OFF + pt * BIAS_STG;
#pragma unroll
            for (int q = 0; q < 8; ++q) {
                const int u = q * 256 + tid;
                const int row = u >> 4, c4 = u & 15;
                CP_ASYNC16(dbase + row * 256 + c4 * 16,
                           bias + (size_t)(ibase + row) * N_TOK + jb2 + c4 * 4);
            }
            CP_COMMIT();
        }

        int st3 = 0;
        for (int t = 0; t < NT_PER_CTA; ++t) {
            const int jb = jbase0 + t * JT;
            if (t >= 3) BAR_SYNC512(4 + st3);        /* P stage empty (t-3 done) */

            CP_WAIT2();                               /* bias tile t landed (mine) */
            BAR_SYNC256(7);                           /* all producers synced */

            /* prefetch bias tile t+3 */
            if (t + 3 < NT_PER_CTA) {
                const int slot = (t + 3) & 3;
                const int jb2 = jbase0 + (t + 3) * JT;
                const uint32_t dbase = sbase + BIAS_OFF + slot * BIAS_STG;
#pragma unroll
                for (int q = 0; q < 8; ++q) {
                    const int u = q * 256 + tid;
                    const int row = u >> 4, c4 = u & 15;
                    CP_ASYNC16(dbase + row * 256 + c4 * 16,
                               bias + (size_t)(ibase + row) * N_TOK + jb2 + c4 * 4);
                }
            }
            CP_COMMIT();

            /* generate P tile: 128 rows x 64 j -> f16 via ex2.f16x2 */
            char* ph = sm + PH_OFF + st3 * PSTG;
            const char* bslot = sm + BIAS_OFF + (t & 3) * BIAS_STG;
            const float4 f2v = *((const float4*)(g_f2 + jb) + jq);
#pragma unroll
            for (int k = 0; k < 8; ++k) {
                const int i = rgrp + k * 16;
                const float2 fc = fcl[i];
                const float4 bv = *(const float4*)(bslot + i * 256 + jq * 16);
                float x, t0, t1, t2, t3;
                x = fc.x + f2v.x; t0 = fmaxf(x, 0.2f * x);
                x = fc.x + f2v.y; t1 = fmaxf(x, 0.2f * x);
                x = fc.x + f2v.z; t2 = fmaxf(x, 0.2f * x);
                x = fc.x + f2v.w; t3 = fmaxf(x, 0.2f * x);
                const float g0 = fmaf(t0, LOG2E, fmaf(bv.x, LOG2E, fc.y));
                const float g1 = fmaf(t1, LOG2E, fmaf(bv.y, LOG2E, fc.y));
                const float g2 = fmaf(t2, LOG2E, fmaf(bv.z, LOG2E, fc.y));
                const float g3 = fmaf(t3, LOG2E, fmaf(bv.w, LOG2E, fc.y));
                *(uint2*)(ph + i * PSTRB + jq * 8) =
                    make_uint2(ex2h2(cvt2h(g0, g1)), ex2h2(cvt2h(g2, g3)));
            }
            BAR_ARRIVE512(1 + st3);                  /* signal P full */
            if (++st3 == 3) st3 = 0;
        }
    } else {
        /* ===================== CONSUMERS (256 thr) ===================== */
        const int cw   = wid - 8;                    /* 0..7 */
        const int rg   = cw & 3;                     /* row group: 32 rows  */
        const int cg2  = cw >> 2;                    /* col group: 32 cols  */
        const int ctid = tid - 256;                  /* 0..255 */
        float acc[2][4][4];                          /* [A-frag][n8][quad]  */
        float accO[2][4];                            /* ones (cg2==1)       */
#pragma unroll
        for (int b = 0; b < 2; ++b) {
#pragma unroll
            for (int n = 0; n < 4; ++n)
#pragma unroll
                for (int q = 0; q < 4; ++q) acc[b][n][q] = 0.f;
#pragma unroll
            for (int q = 0; q < 4; ++q) accO[b][q] = 0.f;
        }

        const uint32_t rsel = (uint32_t)(lane & 15) * PSTRB + (uint32_t)(lane >> 4) * 16;
        const uint32_t vhb = sbase + VH_OFF;

        /* init ones block: V rows 64..79 (col 64 = 1.0, cols 65..79 = 0) */
        for (int u = ctid; u < 16 * 36; u += 256) {
            const int r = u / 36, w = u % 36;
            ((uint32_t*)(sm + VH_OFF + (64 + r) * PSTRB))[w] = (r == 0) ? 0x3C003C00u : 0u;
        }

        int st3 = 0;
        for (int t = 0; t < NT_PER_CTA; ++t) {
            const int jb = jbase0 + t * JT;

            /* issue V loads early (latency hides under the full-wait) */
            uint4 vh_r[2];
#pragma unroll
            for (int r = 0; r < 2; ++r) {
                const int u = r * 256 + ctid;
                const int c = u >> 3, q = u & 7;
                vh_r[r] = *((const uint4*)(g_ftsT + (size_t)c * N_TOK + jb) + q);
            }

            BAR_SYNC512(1 + st3);                    /* P full */

            /* stage V into (single) smem buffer */
#pragma unroll
            for (int r = 0; r < 2; ++r) {
                const int u = r * 256 + ctid;
                const int c = u >> 3, q = u & 7;
                *(uint4*)(sm + VH_OFF + c * PSTRB + q * 16) = vh_r[r];
            }
            BAR_SYNC256(8);                          /* V (+ones) visible */

            const uint32_t ph = sbase + PH_OFF + st3 * PSTG;

#pragma unroll
            for (int ks = 0; ks < 4; ++ks) {
                const uint32_t kofs = (uint32_t)ks * 32;   /* 16 f16 = 32B */
                uint32_t ah0[4], ah1[4];
                ldsm4(ah0[0], ah0[1], ah0[2], ah0[3],
                      ph + (rg * 32) * PSTRB + kofs + rsel);
                ldsm4(ah1[0], ah1[1], ah1[2], ah1[3],
                      ph + (rg * 32 + 16) * PSTRB + kofs + rsel);
                uint32_t b0[4], b1[4];
                ldsm4(b0[0], b0[1], b0[2], b0[3],
                      vhb + ((cg2 * 2) * 16) * PSTRB + kofs + rsel);
                ldsm4(b1[0], b1[1], b1[2], b1[3],
                      vhb + ((cg2 * 2 + 1) * 16) * PSTRB + kofs + rsel);
                mma16816(acc[0][0], ah0, b0[0], b0[2]);
                mma16816(acc[0][1], ah0, b0[1], b0[3]);
                mma16816(acc[0][2], ah0, b1[0], b1[2]);
                mma16816(acc[0][3], ah0, b1[1], b1[3]);
                mma16816(acc[1][0], ah1, b0[0], b0[2]);
                mma16816(acc[1][1], ah1, b0[1], b0[3]);
                mma16816(acc[1][2], ah1, b1[0], b1[2]);
                mma16816(acc[1][3], ah1, b1[1], b1[3]);
                if (cg2 == 1) {                      /* ones block: row sums */
                    uint32_t bo[4];
                    ldsm4(bo[0], bo[1], bo[2], bo[3],
                          vhb + 64 * PSTRB + kofs + rsel);
                    mma16816(accO[0], ah0, bo[0], bo[2]);
                    mma16816(accO[1], ah1, bo[0], bo[2]);
                }
            }
            BAR_ARRIVE512(4 + st3);                  /* signal P empty */
            if (++st3 == 3) st3 = 0;
        }

        /* write partials (rows rg*32.., cols cg2*32..) + denominators */
#pragma unroll
        for (int b = 0; b < 2; ++b) {
            const int m = rg * 32 + b * 16 + (lane >> 2);
            float* dst0 = g_acc + ((size_t)s * N_TOK + ibase + m) * OUTD;
            float* dst8 = dst0 + 8 * OUTD;
#pragma unroll
            for (int n = 0; n < 4; ++n) {
                const int c = cg2 * 32 + n * 8 + (lane & 3) * 2;
                *(float2*)(dst0 + c) = make_float2(acc[b][n][0], acc[b][n][1]);
                *(float2*)(dst8 + c) = make_float2(acc[b][n][2], acc[b][n][3]);
            }
            if (cg2 == 1 && (lane & 3) == 0) {
                g_den[(size_t)s * N_TOK + ibase + m]     = accO[b][0];
                g_den[(size_t)s * N_TOK + ibase + m + 8] = accO[b][2];
            }
        }
    }
}

/* ------------------------------------------------------------------ */
__global__ __launch_bounds__(256) void k4_combine(float* __restrict__ out) {
    const int idx = blockIdx.x * 256 + threadIdx.x;
    if (idx >= N_TOK * 16) return;
    const int i = idx >> 4;
    float den = 0.f;
    float4 a = make_float4(0.f, 0.f, 0.f, 0.f);
#pragma unroll
    for (int s = 0; s < NSPLIT; ++s) {
        den += g_den[s * N_TOK + i];
        const float4 p = ((const float4*)g_acc)[(size_t)s * N_TOK * 16 + idx];
        a.x += p.x; a.y += p.y; a.z += p.z; a.w += p.w;
    }
    const float inv = 1.f / den;
    float4 r = make_float4(a.x * inv, a.y * inv, a.z * inv, a.w * inv);
    r.x = r.x > 0.f ? r.x : expm1f(r.x);
    r.y = r.y > 0.f ? r.y : expm1f(r.y);
    r.z = r.z > 0.f ? r.z : expm1f(r.z);
    r.w = r.w > 0.f ? r.w : expm1f(r.w);
    ((float4*)out)[idx] = r;
}

/* ------------------------------------------------------------------ */
extern "C" void kernel_launch(void* const* d_in, const int* in_sizes, int n_in,
                              void* d_out, int out_size) {
    const float* seq  = (const float*)d_in[0];
    const float* bias = (const float*)d_in[1];
    const float* W1   = (const float*)d_in[2];
    const float* a1   = (const float*)d_in[3];
    const float* b1   = (const float*)d_in[4];
    const float* a2   = (const float*)d_in[5];
    const float* b2   = (const float*)d_in[6];
    float* out = (float*)d_out;

    cudaFuncSetAttribute(k3_attn, cudaFuncAttributeMaxDynamicSharedMemorySize, SMEM3_BYTES);

    k1_fts<<<128, 256>>>(seq, W1, a1, b1, a2, b2);
    k2_max<<<1, 256>>>();
    dim3 g3(N_TOK / M_TILE, NSPLIT);
    k3_attn<<<g3, 512, SMEM3_BYTES>>>(bias);
    k4_combine<<<(N_TOK * 16) / 256, 256>>>(out);
}

// round 10
// speedup vs baseline: 1.0846x; 1.0492x over previous
#include <cuda_runtime.h>
#include <cuda_bf16.h>
#include <cuda_fp16.h>
#include <math.h>
#include <cstdint>

#define N_TOK 8192
#define F_DIM 256
#define OUTD  64
#define NSPLIT 2
#define JCHUNK (N_TOK / NSPLIT)   /* 4096 */
#define M_TILE 128
#define JT 64                     /* j per tile */
#define NT_PER_CTA (JCHUNK / JT)  /* 64 tiles */
#define LOG2E 1.4426950408889634f

/* ---------------- scratch (no allocation allowed) ---------------- */
__device__ __half g_ftsT[OUTD * N_TOK];            /* [c][j] transposed f16 */
__device__ float g_f1[N_TOK];
__device__ float g_f2[N_TOK];
__device__ unsigned g_f2maxu = 0;                  /* ordered-uint max of f2 */
__device__ float g_acc[NSPLIT * N_TOK * OUTD];     /* 4 MB */
__device__ float g_den[NSPLIT * N_TOK];

/* ---------------- helpers ---------------- */
__device__ __forceinline__ uint32_t smem_u32(const void* p) {
    uint32_t a;
    asm("{ .reg .u64 t; cvta.to.shared.u64 t, %1; cvt.u32.u64 %0, t; }" : "=r"(a) : "l"(p));
    return a;
}
/* pack two fp32 -> f16x2 / bf16x2, memory order [a, b] */
__device__ __forceinline__ uint32_t cvt2h(float a, float b) {
    uint32_t r;
    asm("cvt.rn.f16x2.f32 %0, %1, %2;" : "=r"(r) : "f"(b), "f"(a));
    return r;
}
__device__ __forceinline__ uint32_t cvt2bf(float a, float b) {
    uint32_t r;
    asm("cvt.rn.bf16x2.f32 %0, %1, %2;" : "=r"(r) : "f"(b), "f"(a));
    return r;
}
__device__ __forceinline__ float bf_lo_f(uint32_t h) { return __uint_as_float(h << 16); }
__device__ __forceinline__ float bf_hi_f(uint32_t h) { return __uint_as_float(h & 0xFFFF0000u); }
__device__ __forceinline__ uint32_t ex2h2(uint32_t x) {
    uint32_t r;
    asm("ex2.approx.f16x2 %0, %1;" : "=r"(r) : "r"(x));
    return r;
}
__device__ __forceinline__ void ldsm4(uint32_t& r0, uint32_t& r1, uint32_t& r2, uint32_t& r3,
                                      uint32_t addr) {
    asm volatile("ldmatrix.sync.aligned.m8n8.x4.shared.b16 {%0,%1,%2,%3}, [%4];"
                 : "=r"(r0), "=r"(r1), "=r"(r2), "=r"(r3) : "r"(addr));
}
__device__ __forceinline__ void mma16816(float* d, const uint32_t* a, uint32_t b0, uint32_t b1) {
    asm volatile("mma.sync.aligned.m16n8k16.row.col.f32.f16.f16.f32 "
                 "{%0,%1,%2,%3},{%4,%5,%6,%7},{%8,%9},{%0,%1,%2,%3};"
                 : "+f"(d[0]), "+f"(d[1]), "+f"(d[2]), "+f"(d[3])
                 : "r"(a[0]), "r"(a[1]), "r"(a[2]), "r"(a[3]), "r"(b0), "r"(b1));
}
__device__ __forceinline__ void mmabf(float* d, const uint32_t* a, uint32_t b0, uint32_t b1) {
    asm volatile("mma.sync.aligned.m16n8k16.row.col.f32.bf16.bf16.f32 "
                 "{%0,%1,%2,%3},{%4,%5,%6,%7},{%8,%9},{%0,%1,%2,%3};"
                 : "+f"(d[0]), "+f"(d[1]), "+f"(d[2]), "+f"(d[3])
                 : "r"(a[0]), "r"(a[1]), "r"(a[2]), "r"(a[3]), "r"(b0), "r"(b1));
}
/* ordered-uint encode/decode for float max via atomicMax(unsigned) */
__device__ __forceinline__ unsigned f2enc(float f) {
    unsigned u = __float_as_uint(f);
    return (u & 0x80000000u) ? ~u : (u | 0x80000000u);
}
__device__ __forceinline__ float f2dec(unsigned u) {
    unsigned b = (u & 0x80000000u) ? (u & 0x7FFFFFFFu) : ~u;
    return __uint_as_float(b);
}
/* full/empty barriers span producers+consumers = 512 threads */
#define BAR_SYNC512(id)   asm volatile("bar.sync %0, 512;"   :: "r"(id) : "memory")
#define BAR_ARRIVE512(id) asm volatile("bar.arrive %0, 512;" :: "r"(id) : "memory")
#define BAR_SYNC256(id)   asm volatile("bar.sync %0, 256;"   :: "r"(id) : "memory")
#define CP_ASYNC16(dst, src) \
    asm volatile("cp.async.cg.shared.global [%0], [%1], 16;" :: "r"(dst), "l"(src) : "memory")
#define CP_COMMIT() asm volatile("cp.async.commit_group;" ::: "memory")
#define CP_WAIT2()  asm volatile("cp.async.wait_group 2;" ::: "memory")

/* ------------------------------------------------------------------ */
/* k1: seq_fts = seq @ W1 via bf16x3 split HMMA -> g_ftsT f16, f1, f2, */
/* and global max(f2) via ordered atomicMax (k2 merged).               */
/* grid 128 CTAs x 256 thr; CTA = 64 rows x 64 cols, K=256.            */
/* ------------------------------------------------------------------ */
#define K1_AH 0                   /* 4 kb x 64 rows x 144B = 36864 */
#define K1_AL 36864
#define K1_BH 73728
#define K1_BL 110592
#define K1_A1 147456              /* 64 f32 */
#define K1_A2 147712
#define K1_F1P 147968             /* 2 x 64 f32 */
#define K1_F2P 148480
#define SMEM1_BYTES 148992

__global__ __launch_bounds__(256, 1) void k1_fts(const float* __restrict__ seq,
        const float* __restrict__ W1, const float* __restrict__ a1,
        const float* __restrict__ b1, const float* __restrict__ a2,
        const float* __restrict__ b2) {
    extern __shared__ char sm[];
    const uint32_t sbase = smem_u32(sm);
    __shared__ unsigned lmax_s;

    const int tid = threadIdx.x;
    const int wid = tid >> 5, lane = tid & 31;
    const int rb  = blockIdx.x * 64;

    if (tid == 0) lmax_s = 0u;
    if (tid < OUTD) {
        ((float*)(sm + K1_A1))[tid] = a1[tid];
        ((float*)(sm + K1_A2))[tid] = a2[tid];
    }

    /* convert A (seq tile 64x256) to bf16 hi/lo, 144-stride blocked layout */
#pragma unroll
    for (int i = 0; i < 16; ++i) {
        const int u = i * 256 + tid;
        const int m = u >> 6, ch = u & 63;          /* ch = float4 index in row */
        const int kb = ch >> 4, kw = ch & 15;
        const float4 v = *((const float4*)(seq + (size_t)(rb + m) * F_DIM) + ch);
        const uint32_t h01 = cvt2bf(v.x, v.y), h23 = cvt2bf(v.z, v.w);
        const float e0 = v.x - bf_lo_f(h01), e1 = v.y - bf_hi_f(h01);
        const float e2 = v.z - bf_lo_f(h23), e3 = v.w - bf_hi_f(h23);
        char* dh = sm + K1_AH + kb * 9216 + m * 144 + kw * 8;
        char* dl = sm + K1_AL + kb * 9216 + m * 144 + kw * 8;
        *(uint2*)dh = make_uint2(h01, h23);
        *(uint2*)dl = make_uint2(cvt2bf(e0, e1), cvt2bf(e2, e3));
    }

    /* convert B = W1^T (64 n-rows x 256 k) to bf16 hi/lo */
    {
        const int n = tid & 63, kq = tid >> 6;      /* kq = k-block 0..3 */
        const float* wp = W1 + n;
        char* dh = sm + K1_BH + kq * 9216 + n * 144;
        char* dl = sm + K1_BL + kq * 9216 + n * 144;
#pragma unroll 8
        for (int kk = 0; kk < 64; kk += 2) {
            const float w0 = wp[(size_t)(kq * 64 + kk) * OUTD];
            const float w1 = wp[(size_t)(kq * 64 + kk + 1) * OUTD];
            const uint32_t h = cvt2bf(w0, w1);
            const float e0 = w0 - bf_lo_f(h), e1 = w1 - bf_hi_f(h);
            *(uint32_t*)(dh + kk * 2) = h;
            *(uint32_t*)(dl + kk * 2) = cvt2bf(e0, e1);
        }
    }
    __syncthreads();

    /* MMA: warp -> 16 rows x 32 cols; 16 ksteps x 3 products */
    const int rg  = (wid & 3) * 16;
    const int cgb = (wid >> 2) * 32;
    const uint32_t rsel = (uint32_t)(lane & 15) * 144 + (uint32_t)(lane >> 4) * 16;
    float acc[4][4];
#pragma unroll
    for (int n = 0; n < 4; ++n)
#pragma unroll
        for (int q = 0; q < 4; ++q) acc[n][q] = 0.f;

#pragma unroll
    for (int ks = 0; ks < 16; ++ks) {
        const uint32_t boff = (uint32_t)(ks >> 2) * 9216 + (uint32_t)(ks & 3) * 32;
        uint32_t ah[4], al[4], bh0[4], bh1[4], bl0[4], bl1[4];
        ldsm4(ah[0], ah[1], ah[2], ah[3], sbase + K1_AH + boff + rg * 144 + rsel);
        ldsm4(al[0], al[1], al[2], al[3], sbase + K1_AL + boff + rg * 144 + rsel);
        ldsm4(bh0[0], bh0[1], bh0[2], bh0[3], sbase + K1_BH + boff + cgb * 144 + rsel);
        ldsm4(bh1[0], bh1[1], bh1[2], bh1[3], sbase + K1_BH + boff + (cgb + 16) * 144 + rsel);
        ldsm4(bl0[0], bl0[1], bl0[2], bl0[3], sbase + K1_BL + boff + cgb * 144 + rsel);
        ldsm4(bl1[0], bl1[1], bl1[2], bl1[3], sbase + K1_BL + boff + (cgb + 16) * 144 + rsel);
        mmabf(acc[0], ah, bh0[0], bh0[2]);
        mmabf(acc[0], ah, bl0[0], bl0[2]);
        mmabf(acc[0], al, bh0[0], bh0[2]);
        mmabf(acc[1], ah, bh0[1], bh0[3]);
        mmabf(acc[1], ah, bl0[1], bl0[3]);
        mmabf(acc[1], al, bh0[1], bh0[3]);
        mmabf(acc[2], ah, bh1[0], bh1[2]);
        mmabf(acc[2], ah, bl1[0], bl1[2]);
        mmabf(acc[2], al, bh1[0], bh1[2]);
        mmabf(acc[3], ah, bh1[1], bh1[3]);
        mmabf(acc[3], ah, bl1[1], bl1[3]);
        mmabf(acc[3], al, bh1[1], bh1[3]);
    }

    /* epilogue: f1/f2 partials + transposed f16 fts store */
    const float* a1s = (const float*)(sm + K1_A1);
    const float* a2s = (const float*)(sm + K1_A2);
    float* f1p = (float*)(sm + K1_F1P);
    float* f2p = (float*)(sm + K1_F2P);
    const int r  = lane >> 2;
    const int cq = (lane & 3) * 2;

#pragma unroll
    for (int h = 0; h < 2; ++h) {
        const int mloc = rg + r + h * 8;
        float p1 = 0.f, p2 = 0.f;
#pragma unroll
        for (int n = 0; n < 4; ++n) {
            const int c = cgb + n * 8 + cq;
            p1 += acc[n][2 * h] * a1s[c] + acc[n][2 * h + 1] * a1s[c + 1];
            p2 += acc[n][2 * h] * a2s[c] + acc[n][2 * h + 1] * a2s[c + 1];
        }
        p1 += __shfl_xor_sync(0xffffffffu, p1, 1);
        p1 += __shfl_xor_sync(0xffffffffu, p1, 2);
        p2 += __shfl_xor_sync(0xffffffffu, p2, 1);
        p2 += __shfl_xor_sync(0xffffffffu, p2, 2);
        if ((lane & 3) == 0) {
            f1p[(wid >> 2) * 64 + mloc] = p1;
            f2p[(wid >> 2) * 64 + mloc] = p2;
        }
        /* fts store (transposed): g_ftsT[c][rb+m] */
        const int m = rb + mloc;
#pragma unroll
        for (int n = 0; n < 4; ++n) {
            const int c = cgb + n * 8 + cq;
            g_ftsT[(size_t)c * N_TOK + m]       = __float2half(acc[n][2 * h]);
            g_ftsT[(size_t)(c + 1) * N_TOK + m] = __float2half(acc[n][2 * h + 1]);
        }
    }
    __syncthreads();

    if (tid < 64) {
        const float f1 = f1p[tid] + f1p[64 + tid] + b1[0];
        const float f2 = f2p[tid] + f2p[64 + tid] + b2[0];
        g_f1[rb + tid] = f1;
        g_f2[rb + tid] = f2;
        atomicMax(&lmax_s, f2enc(f2));
    }
    __syncthreads();
    if (tid == 0) atomicMax(&g_f2maxu, lmax_s);
}

/* ------------------------------------------------------------------ */
/* k3: 512 threads: warps 0-7 produce P (bias ring + ex2.f16x2),       */
/* warps 8-15 consume with 4x2 row/col split. 3-stage P ring.          */
/* Denominator via ones-col MMA (col-group 1 only).                    */
/* ------------------------------------------------------------------ */
#define PSTRB 144                 /* bytes per smem tile row (72 f16) */
#define PSTG  18432               /* 128*144 */
#define PH_OFF 0                  /* 3 stages */
#define VH_OFF (3 * PSTG)         /* 55296: 80 rows x 144 = 11520 */
#define FCL_OFF 66816             /* 128 x float2 = 1024 */
#define BIAS_OFF 67840            /* 4 stages x 32768 */
#define BIAS_STG 32768
#define SMEM3_BYTES (BIAS_OFF + 4 * BIAS_STG)   /* 198912 */

__global__ __launch_bounds__(512, 1) void k3_attn(const float* __restrict__ bias) {
    extern __shared__ char sm[];
    const uint32_t sbase = smem_u32(sm);
    float2* fcl = (float2*)(sm + FCL_OFF);        /* {f1, -m*log2e} per row */

    const int tid  = threadIdx.x;
    const int wid  = tid >> 5, lane = tid & 31;
    const int ibase = blockIdx.x * M_TILE;
    const int s     = blockIdx.y;
    const int jbase0 = s * JCHUNK;

    if (tid < M_TILE) {
        const float f1v = g_f1[ibase + tid];
        const float f2m = f2dec(g_f2maxu);
        const float x = f1v + f2m;
        fcl[tid] = make_float2(f1v, -fmaxf(x, 0.2f * x) * LOG2E);
    }
    __syncthreads();

    if (wid < 8) {
        /* ===================== PRODUCERS (256 thr) ===================== */
        const int jq    = lane & 15;
        const int rgrp  = wid * 2 + (lane >> 4);     /* 0..15 */

        /* prologue: prefetch bias tiles 0,1,2 */
#pragma unroll
        for (int pt = 0; pt < 3; ++pt) {
            const int jb2 = jbase0 + pt * JT;
            const uint32_t dbase = sbase + BIAS_OFF + pt * BIAS_STG;
#pragma unroll
            for (int q = 0; q < 8; ++q) {
                const int u = q * 256 + tid;
                const int row = u >> 4, c4 = u & 15;
                CP_ASYNC16(dbase + row * 256 + c4 * 16,
                           bias + (size_t)(ibase + row) * N_TOK + jb2 + c4 * 4);
            }
            CP_COMMIT();
        }

        int st3 = 0;
        for (int t = 0; t < NT_PER_CTA; ++t) {
            const int jb = jbase0 + t * JT;
            if (t >= 3) BAR_SYNC512(4 + st3);        /* P stage empty (t-3 done) */

            CP_WAIT2();                               /* bias tile t landed (mine) */
            BAR_SYNC256(7);                           /* all producers synced */

            /* prefetch bias tile t+3 */
            if (t + 3 < NT_PER_CTA) {
                const int slot = (t + 3) & 3;
                const int jb2 = jbase0 + (t + 3) * JT;
                const uint32_t dbase = sbase + BIAS_OFF + slot * BIAS_STG;
#pragma unroll
                for (int q = 0; q < 8; ++q) {
                    const int u = q * 256 + tid;
                    const int row = u >> 4, c4 = u & 15;
                    CP_ASYNC16(dbase + row * 256 + c4 * 16,
                               bias + (size_t)(ibase + row) * N_TOK + jb2 + c4 * 4);
                }
            }
            CP_COMMIT();

            /* generate P tile: 128 rows x 64 j -> f16 via ex2.f16x2 */
            char* ph = sm + PH_OFF + st3 * PSTG;
            const char* bslot = sm + BIAS_OFF + (t & 3) * BIAS_STG;
            const float4 f2v = *((const float4*)(g_f2 + jb) + jq);
#pragma unroll
            for (int k = 0; k < 8; ++k) {
                const int i = rgrp + k * 16;
                const float2 fc = fcl[i];
                const float4 bv = *(const float4*)(bslot + i * 256 + jq * 16);
                float x, t0, t1, t2, t3;
                x = fc.x + f2v.x; t0 = fmaxf(x, 0.2f * x);
                x = fc.x + f2v.y; t1 = fmaxf(x, 0.2f * x);
                x = fc.x + f2v.z; t2 = fmaxf(x, 0.2f * x);
                x = fc.x + f2v.w; t3 = fmaxf(x, 0.2f * x);
                const float g0 = fmaf(t0, LOG2E, fmaf(bv.x, LOG2E, fc.y));
                const float g1 = fmaf(t1, LOG2E, fmaf(bv.y, LOG2E, fc.y));
                const float g2 = fmaf(t2, LOG2E, fmaf(bv.z, LOG2E, fc.y));
                const float g3 = fmaf(t3, LOG2E, fmaf(bv.w, LOG2E, fc.y));
                *(uint2*)(ph + i * PSTRB + jq * 8) =
                    make_uint2(ex2h2(cvt2h(g0, g1)), ex2h2(cvt2h(g2, g3)));
            }
            BAR_ARRIVE512(1 + st3);                  /* signal P full */
            if (++st3 == 3) st3 = 0;
        }
    } else {
        /* ===================== CONSUMERS (256 thr) ===================== */
        const int cw   = wid - 8;                    /* 0..7 */
        const int rg   = cw & 3;                     /* row group: 32 rows  */
        const int cg2  = cw >> 2;                    /* col group: 32 cols  */
        const int ctid = tid - 256;                  /* 0..255 */
        float acc[2][4][4];
        float accO[2][4];
#pragma unroll
        for (int b = 0; b < 2; ++b) {
#pragma unroll
            for (int n = 0; n < 4; ++n)
#pragma unroll
                for (int q = 0; q < 4; ++q) acc[b][n][q] = 0.f;
#pragma unroll
            for (int q = 0; q < 4; ++q) accO[b][q] = 0.f;
        }

        const uint32_t rsel = (uint32_t)(lane & 15) * PSTRB + (uint32_t)(lane >> 4) * 16;
        const uint32_t vhb = sbase + VH_OFF;

        /* init ones block: V rows 64..79 (col 64 = 1.0, cols 65..79 = 0) */
        for (int u = ctid; u < 16 * 36; u += 256) {
            const int r = u / 36, w = u % 36;
            ((uint32_t*)(sm + VH_OFF + (64 + r) * PSTRB))[w] = (r == 0) ? 0x3C003C00u : 0u;
        }

        int st3 = 0;
        for (int t = 0; t < NT_PER_CTA; ++t) {
            const int jb = jbase0 + t * JT;

            /* issue V loads early (latency hides under the full-wait) */
            uint4 vh_r[2];
#pragma unroll
            for (int r = 0; r < 2; ++r) {
                const int u = r * 256 + ctid;
                const int c = u >> 3, q = u & 7;
                vh_r[r] = *((const uint4*)(g_ftsT + (size_t)c * N_TOK + jb) + q);
            }

            BAR_SYNC512(1 + st3);                    /* P full */

            /* stage V into (single) smem buffer */
#pragma unroll
            for (int r = 0; r < 2; ++r) {
                const int u = r * 256 + ctid;
                const int c = u >> 3, q = u & 7;
                *(uint4*)(sm + VH_OFF + c * PSTRB + q * 16) = vh_r[r];
            }
            BAR_SYNC256(8);                          /* V (+ones) visible */

            const uint32_t ph = sbase + PH_OFF + st3 * PSTG;

#pragma unroll
            for (int ks = 0; ks < 4; ++ks) {
                const uint32_t kofs = (uint32_t)ks * 32;   /* 16 f16 = 32B */
                uint32_t ah0[4], ah1[4];
                ldsm4(ah0[0], ah0[1], ah0[2], ah0[3],
                      ph + (rg * 32) * PSTRB + kofs + rsel);
                ldsm4(ah1[0], ah1[1], ah1[2], ah1[3],
                      ph + (rg * 32 + 16) * PSTRB + kofs + rsel);
                uint32_t b0[4], b1[4];
                ldsm4(b0[0], b0[1], b0[2], b0[3],
                      vhb + ((cg2 * 2) * 16) * PSTRB + kofs + rsel);
                ldsm4(b1[0], b1[1], b1[2], b1[3],
                      vhb + ((cg2 * 2 + 1) * 16) * PSTRB + kofs + rsel);
                mma16816(acc[0][0], ah0, b0[0], b0[2]);
                mma16816(acc[0][1], ah0, b0[1], b0[3]);
                mma16816(acc[0][2], ah0, b1[0], b1[2]);
                mma16816(acc[0][3], ah0, b1[1], b1[3]);
                mma16816(acc[1][0], ah1, b0[0], b0[2]);
                mma16816(acc[1][1], ah1, b0[1], b0[3]);
                mma16816(acc[1][2], ah1, b1[0], b1[2]);
                mma16816(acc[1][3], ah1, b1[1], b1[3]);
                if (cg2 == 1) {                      /* ones block: row sums */
                    uint32_t bo[4];
                    ldsm4(bo[0], bo[1], bo[2], bo[3],
                          vhb + 64 * PSTRB + kofs + rsel);
                    mma16816(accO[0], ah0, bo[0], bo[2]);
                    mma16816(accO[1], ah1, bo[0], bo[2]);
                }
            }
            BAR_ARRIVE512(4 + st3);                  /* signal P empty */
            if (++st3 == 3) st3 = 0;
        }

        /* write partials (rows rg*32.., cols cg2*32..) + denominators */
#pragma unroll
        for (int b = 0; b < 2; ++b) {
            const int m = rg * 32 + b * 16 + (lane >> 2);
            float* dst0 = g_acc + ((size_t)s * N_TOK + ibase + m) * OUTD;
            float* dst8 = dst0 + 8 * OUTD;
#pragma unroll
            for (int n = 0; n < 4; ++n) {
                const int c = cg2 * 32 + n * 8 + (lane & 3) * 2;
                *(float2*)(dst0 + c) = make_float2(acc[b][n][0], acc[b][n][1]);
                *(float2*)(dst8 + c) = make_float2(acc[b][n][2], acc[b][n][3]);
            }
            if (cg2 == 1 && (lane & 3) == 0) {
                g_den[(size_t)s * N_TOK + ibase + m]     = accO[b][0];
                g_den[(size_t)s * N_TOK + ibase + m + 8] = accO[b][2];
            }
        }
    }
}

/* ------------------------------------------------------------------ */
__global__ __launch_bounds__(256) void k4_combine(float* __restrict__ out) {
    const int idx = blockIdx.x * 256 + threadIdx.x;
    if (blockIdx.x == 0 && threadIdx.x == 0) g_f2maxu = 0u;  /* reset for next replay */
    if (idx >= N_TOK * 16) return;
    const int i = idx >> 4;
    float den = 0.f;
    float4 a = make_float4(0.f, 0.f, 0.f, 0.f);
#pragma unroll
    for (int s = 0; s < NSPLIT; ++s) {
        den += g_den[s * N_TOK + i];
        const float4 p = ((const float4*)g_acc)[(size_t)s * N_TOK * 16 + idx];
        a.x += p.x; a.y += p.y; a.z += p.z; a.w += p.w;
    }
    const float inv = 1.f / den;
    float4 r = make_float4(a.x * inv, a.y * inv, a.z * inv, a.w * inv);
    r.x = r.x > 0.f ? r.x : expm1f(r.x);
    r.y = r.y > 0.f ? r.y : expm1f(r.y);
    r.z = r.z > 0.f ? r.z : expm1f(r.z);
    r.w = r.w > 0.f ? r.w : expm1f(r.w);
    ((float4*)out)[idx] = r;
}

/* ------------------------------------------------------------------ */
extern "C" void kernel_launch(void* const* d_in, const int* in_sizes, int n_in,
                              void* d_out, int out_size) {
    const float* seq  = (const float*)d_in[0];
    const float* bias = (const float*)d_in[1];
    const float* W1   = (const float*)d_in[2];
    const float* a1   = (const float*)d_in[3];
    const float* b1   = (const float*)d_in[4];
    const float* a2   = (const float*)d_in[5];
    const float* b2   = (const float*)d_in[6];
    float* out = (float*)d_out;

    cudaFuncSetAttribute(k1_fts,  cudaFuncAttributeMaxDynamicSharedMemorySize, SMEM1_BYTES);
    cudaFuncSetAttribute(k3_attn, cudaFuncAttributeMaxDynamicSharedMemorySize, SMEM3_BYTES);

    k1_fts<<<128, 256, SMEM1_BYTES>>>(seq, W1, a1, b1, a2, b2);
    dim3 g3(N_TOK / M_TILE, NSPLIT);
    k3_attn<<<g3, 512, SMEM3_BYTES>>>(bias);
    k4_combine<<<(N_TOK * 16) / 256, 256>>>(out);
}

// round 11
// speedup vs baseline: 1.1506x; 1.0608x over previous
#include <cuda_runtime.h>
#include <cuda_bf16.h>
#include <cuda_fp16.h>
#include <math.h>
#include <cstdint>

#define N_TOK 8192
#define F_DIM 256
#define OUTD  64
#define NSPLIT 2
#define JCHUNK (N_TOK / NSPLIT)   /* 4096 */
#define M_TILE 128
#define JT 64                     /* j per tile */
#define NT_PER_CTA (JCHUNK / JT)  /* 64 tiles */
#define LOG2E 1.4426950408889634f

/* ---------------- scratch (no allocation allowed) ---------------- */
__device__ __half g_ftsT[OUTD * N_TOK];            /* [c][j] transposed f16 */
__device__ float g_f1[N_TOK];
__device__ float g_f2[N_TOK];
__device__ unsigned g_f2maxu = 0;                  /* ordered-uint max of f2 */
__device__ float g_acc[NSPLIT * N_TOK * OUTD];     /* 4 MB */
__device__ float g_den[NSPLIT * N_TOK];

/* ---------------- helpers ---------------- */
__device__ __forceinline__ uint32_t smem_u32(const void* p) {
    uint32_t a;
    asm("{ .reg .u64 t; cvta.to.shared.u64 t, %1; cvt.u32.u64 %0, t; }" : "=r"(a) : "l"(p));
    return a;
}
/* pack two fp32 -> f16x2 / bf16x2, memory order [a, b] */
__device__ __forceinline__ uint32_t cvt2h(float a, float b) {
    uint32_t r;
    asm("cvt.rn.f16x2.f32 %0, %1, %2;" : "=r"(r) : "f"(b), "f"(a));
    return r;
}
__device__ __forceinline__ uint32_t cvt2bf(float a, float b) {
    uint32_t r;
    asm("cvt.rn.bf16x2.f32 %0, %1, %2;" : "=r"(r) : "f"(b), "f"(a));
    return r;
}
__device__ __forceinline__ float bf_lo_f(uint32_t h) { return __uint_as_float(h << 16); }
__device__ __forceinline__ float bf_hi_f(uint32_t h) { return __uint_as_float(h & 0xFFFF0000u); }
__device__ __forceinline__ uint32_t ex2h2(uint32_t x) {
    uint32_t r;
    asm("ex2.approx.f16x2 %0, %1;" : "=r"(r) : "r"(x));
    return r;
}
__device__ __forceinline__ void ldsm4(uint32_t& r0, uint32_t& r1, uint32_t& r2, uint32_t& r3,
                                      uint32_t addr) {
    asm volatile("ldmatrix.sync.aligned.m8n8.x4.shared.b16 {%0,%1,%2,%3}, [%4];"
                 : "=r"(r0), "=r"(r1), "=r"(r2), "=r"(r3) : "r"(addr));
}
__device__ __forceinline__ void mma16816(float* d, const uint32_t* a, uint32_t b0, uint32_t b1) {
    asm volatile("mma.sync.aligned.m16n8k16.row.col.f32.f16.f16.f32 "
                 "{%0,%1,%2,%3},{%4,%5,%6,%7},{%8,%9},{%0,%1,%2,%3};"
                 : "+f"(d[0]), "+f"(d[1]), "+f"(d[2]), "+f"(d[3])
                 : "r"(a[0]), "r"(a[1]), "r"(a[2]), "r"(a[3]), "r"(b0), "r"(b1));
}
__device__ __forceinline__ void mmabf(float* d, const uint32_t* a, uint32_t b0, uint32_t b1) {
    asm volatile("mma.sync.aligned.m16n8k16.row.col.f32.bf16.bf16.f32 "
                 "{%0,%1,%2,%3},{%4,%5,%6,%7},{%8,%9},{%0,%1,%2,%3};"
                 : "+f"(d[0]), "+f"(d[1]), "+f"(d[2]), "+f"(d[3])
                 : "r"(a[0]), "r"(a[1]), "r"(a[2]), "r"(a[3]), "r"(b0), "r"(b1));
}
/* ordered-uint encode/decode for float max via atomicMax(unsigned) */
__device__ __forceinline__ unsigned f2enc(float f) {
    unsigned u = __float_as_uint(f);
    return (u & 0x80000000u) ? ~u : (u | 0x80000000u);
}
__device__ __forceinline__ float f2dec(unsigned u) {
    unsigned b = (u & 0x80000000u) ? (u & 0x7FFFFFFFu) : ~u;
    return __uint_as_float(b);
}
#define BAR_SYNC512(id)   asm volatile("bar.sync %0, 512;"   :: "r"(id) : "memory")
#define BAR_ARRIVE512(id) asm volatile("bar.arrive %0, 512;" :: "r"(id) : "memory")
#define BAR_SYNC256(id)   asm volatile("bar.sync %0, 256;"   :: "r"(id) : "memory")
#define CP_ASYNC16(dst, src) \
    asm volatile("cp.async.cg.shared.global [%0], [%1], 16;" :: "r"(dst), "l"(src) : "memory")
#define CP_COMMIT() asm volatile("cp.async.commit_group;" ::: "memory")
#define CP_WAIT2()  asm volatile("cp.async.wait_group 2;" ::: "memory")

/* ------------------------------------------------------------------ */
/* k1: seq_fts = seq @ W1 via bf16x3 split HMMA (512 thr, 16x16 warp   */
/* tiles); coalesced W1 conversion; smem-staged transposed f16 store;  */
/* f1/f2 + global max(f2) fused.                                       */
/* ------------------------------------------------------------------ */
#define K1_AH 0                   /* 4 kb x 64 rows x 144B = 36864 */
#define K1_AL 36864
#define K1_BH 73728
#define K1_BL 110592
#define K1_FTS 147456             /* [m][c] stage: 64 x 132B = 8448 */
#define K1_A1 155904              /* 64 f32 */
#define K1_A2 156160
#define K1_F1P 156416             /* 4 x 64 f32 */
#define K1_F2P 157440
#define SMEM1_BYTES 158464

__global__ __launch_bounds__(512, 1) void k1_fts(const float* __restrict__ seq,
        const float* __restrict__ W1, const float* __restrict__ a1,
        const float* __restrict__ b1, const float* __restrict__ a2,
        const float* __restrict__ b2) {
    extern __shared__ char sm[];
    const uint32_t sbase = smem_u32(sm);
    __shared__ unsigned lmax_s;

    const int tid = threadIdx.x;
    const int wid = tid >> 5, lane = tid & 31;
    const int rb  = blockIdx.x * 64;

    if (tid == 0) lmax_s = 0u;
    if (tid < OUTD) {
        ((float*)(sm + K1_A1))[tid] = a1[tid];
        ((float*)(sm + K1_A2))[tid] = a2[tid];
    }

    /* convert A (seq tile 64x256) to bf16 hi/lo, 144-stride blocked layout */
#pragma unroll
    for (int i = 0; i < 8; ++i) {
        const int u = i * 512 + tid;
        const int m = u >> 6, ch = u & 63;
        const int kb = ch >> 4, kw = ch & 15;
        const float4 v = *((const float4*)(seq + (size_t)(rb + m) * F_DIM) + ch);
        const uint32_t h01 = cvt2bf(v.x, v.y), h23 = cvt2bf(v.z, v.w);
        const float e0 = v.x - bf_lo_f(h01), e1 = v.y - bf_hi_f(h01);
        const float e2 = v.z - bf_lo_f(h23), e3 = v.w - bf_hi_f(h23);
        char* dh = sm + K1_AH + kb * 9216 + m * 144 + kw * 8;
        char* dl = sm + K1_AL + kb * 9216 + m * 144 + kw * 8;
        *(uint2*)dh = make_uint2(h01, h23);
        *(uint2*)dl = make_uint2(cvt2bf(e0, e1), cvt2bf(e2, e3));
    }

    /* convert B = W1^T to bf16 hi/lo: coalesced float4 pairs along k */
#pragma unroll
    for (int i = 0; i < 4; ++i) {
        const int u = i * 512 + tid;
        const int n4 = u >> 7, k2g = u & 127;
        const int k = k2g * 2;
        const float4 v0 = *((const float4*)(W1 + (size_t)k * OUTD) + n4);
        const float4 v1 = *((const float4*)(W1 + (size_t)(k + 1) * OUTD) + n4);
        const int kb = k >> 6, koff = k & 63;
        const float* p0 = &v0.x;
        const float* p1 = &v1.x;
#pragma unroll
        for (int nn = 0; nn < 4; ++nn) {
            const int n = n4 * 4 + nn;
            const uint32_t h = cvt2bf(p0[nn], p1[nn]);
            const float e0 = p0[nn] - bf_lo_f(h), e1 = p1[nn] - bf_hi_f(h);
            *(uint32_t*)(sm + K1_BH + kb * 9216 + n * 144 + koff * 2) = h;
            *(uint32_t*)(sm + K1_BL + kb * 9216 + n * 144 + koff * 2) = cvt2bf(e0, e1);
        }
    }
    __syncthreads();

    /* MMA: warp -> 16 rows x 16 cols; 16 ksteps x 3 products */
    const int rg  = (wid & 3) * 16;
    const int cgb = (wid >> 2) * 16;
    const uint32_t rsel = (uint32_t)(lane & 15) * 144 + (uint32_t)(lane >> 4) * 16;
    float acc[2][4];
#pragma unroll
    for (int n = 0; n < 2; ++n)
#pragma unroll
        for (int q = 0; q < 4; ++q) acc[n][q] = 0.f;

#pragma unroll
    for (int ks = 0; ks < 16; ++ks) {
        const uint32_t boff = (uint32_t)(ks >> 2) * 9216 + (uint32_t)(ks & 3) * 32;
        uint32_t ah[4], al[4], bh[4], bl[4];
        ldsm4(ah[0], ah[1], ah[2], ah[3], sbase + K1_AH + boff + rg * 144 + rsel);
        ldsm4(al[0], al[1], al[2], al[3], sbase + K1_AL + boff + rg * 144 + rsel);
        ldsm4(bh[0], bh[1], bh[2], bh[3], sbase + K1_BH + boff + cgb * 144 + rsel);
        ldsm4(bl[0], bl[1], bl[2], bl[3], sbase + K1_BL + boff + cgb * 144 + rsel);
        mmabf(acc[0], ah, bh[0], bh[2]);
        mmabf(acc[0], ah, bl[0], bl[2]);
        mmabf(acc[0], al, bh[0], bh[2]);
        mmabf(acc[1], ah, bh[1], bh[3]);
        mmabf(acc[1], ah, bl[1], bl[3]);
        mmabf(acc[1], al, bh[1], bh[3]);
    }

    /* epilogue: f1/f2 partials + stage fts tile [m][c] in smem */
    const float* a1s = (const float*)(sm + K1_A1);
    const float* a2s = (const float*)(sm + K1_A2);
    float* f1p = (float*)(sm + K1_F1P);
    float* f2p = (float*)(sm + K1_F2P);
    const int r  = lane >> 2;
    const int cq = (lane & 3) * 2;

#pragma unroll
    for (int h = 0; h < 2; ++h) {
        const int m = rg + r + h * 8;
        float p1 = acc[0][2 * h] * a1s[cgb + cq] + acc[0][2 * h + 1] * a1s[cgb + cq + 1]
                 + acc[1][2 * h] * a1s[cgb + 8 + cq] + acc[1][2 * h + 1] * a1s[cgb + 8 + cq + 1];
        float p2 = acc[0][2 * h] * a2s[cgb + cq] + acc[0][2 * h + 1] * a2s[cgb + cq + 1]
                 + acc[1][2 * h] * a2s[cgb + 8 + cq] + acc[1][2 * h + 1] * a2s[cgb + 8 + cq + 1];
        p1 += __shfl_xor_sync(0xffffffffu, p1, 1);
        p1 += __shfl_xor_sync(0xffffffffu, p1, 2);
        p2 += __shfl_xor_sync(0xffffffffu, p2, 1);
        p2 += __shfl_xor_sync(0xffffffffu, p2, 2);
        if ((lane & 3) == 0) {
            f1p[(wid >> 2) * 64 + m] = p1;
            f2p[(wid >> 2) * 64 + m] = p2;
        }
        *(uint32_t*)(sm + K1_FTS + m * 132 + (cgb + cq) * 2) =
            cvt2h(acc[0][2 * h], acc[0][2 * h + 1]);
        *(uint32_t*)(sm + K1_FTS + m * 132 + (cgb + 8 + cq) * 2) =
            cvt2h(acc[1][2 * h], acc[1][2 * h + 1]);
    }
    __syncthreads();

    /* coalesced transposed store: g_ftsT[c][rb+m] */
    {
        const int c = tid >> 3, mg = tid & 7;
        uint32_t w[4];
#pragma unroll
        for (int p = 0; p < 4; ++p) {
            const uint32_t u0 = *(const uint16_t*)(sm + K1_FTS + (mg * 8 + 2 * p) * 132 + c * 2);
            const uint32_t u1 = *(const uint16_t*)(sm + K1_FTS + (mg * 8 + 2 * p + 1) * 132 + c * 2);
            w[p] = u0 | (u1 << 16);
        }
        *((uint4*)(g_ftsT + (size_t)c * N_TOK + rb + mg * 8)) = make_uint4(w[0], w[1], w[2], w[3]);
    }

    if (tid < 64) {
        const float f1 = f1p[tid] + f1p[64 + tid] + f1p[128 + tid] + f1p[192 + tid] + b1[0];
        const float f2 = f2p[tid] + f2p[64 + tid] + f2p[128 + tid] + f2p[192 + tid] + b2[0];
        g_f1[rb + tid] = f1;
        g_f2[rb + tid] = f2;
        atomicMax(&lmax_s, f2enc(f2));
    }
    __syncthreads();
    if (tid == 0) atomicMax(&g_f2maxu, lmax_s);
}

/* ------------------------------------------------------------------ */
/* k3: 512 threads: warps 0-7 produce P (per-warp-owned bias rows +    */
/* ex2.f16x2), warps 8-15 consume (4x2 row/col split). 3-stage P ring. */
/* ------------------------------------------------------------------ */
#define PSTRB 144                 /* bytes per smem tile row (72 f16) */
#define PSTG  18432               /* 128*144 */
#define PH_OFF 0                  /* 3 stages */
#define VH_OFF (3 * PSTG)         /* 55296: 80 rows x 144 = 11520 */
#define FCL_OFF 66816             /* 128 x float2 = 1024 */
#define BIAS_OFF 67840            /* 4 stages x 32768 */
#define BIAS_STG 32768
#define SMEM3_BYTES (BIAS_OFF + 4 * BIAS_STG)   /* 198912 */

__global__ __launch_bounds__(512, 1) void k3_attn(const float* __restrict__ bias) {
    extern __shared__ char sm[];
    const uint32_t sbase = smem_u32(sm);
    float2* fcl = (float2*)(sm + FCL_OFF);        /* {f1, -m*log2e} per row */

    const int tid  = threadIdx.x;
    const int wid  = tid >> 5, lane = tid & 31;
    const int ibase = blockIdx.x * M_TILE;
    const int s     = blockIdx.y;
    const int jbase0 = s * JCHUNK;

    if (tid < M_TILE) {
        const float f1v = g_f1[ibase + tid];
        const float f2m = f2dec(g_f2maxu);
        const float x = f1v + f2m;
        fcl[tid] = make_float2(f1v, -fmaxf(x, 0.2f * x) * LOG2E);
    }
    __syncthreads();

    if (wid < 8) {
        /* ===================== PRODUCERS (256 thr) ===================== */
        /* warp w owns bias/P rows w*16 .. w*16+15 (within-warp pipeline)  */
        const int jq    = lane & 15;
        const int rhalf = lane >> 4;

        /* prologue: prefetch bias tiles 0,1,2 (warp-owned rows) */
#pragma unroll
        for (int pt = 0; pt < 3; ++pt) {
            const int jb2 = jbase0 + pt * JT;
            const uint32_t dbase = sbase + BIAS_OFF + pt * BIAS_STG;
#pragma unroll
            for (int q = 0; q < 8; ++q) {
                const int row = wid * 16 + q * 2 + rhalf;
                CP_ASYNC16(dbase + row * 256 + jq * 16,
                           bias + (size_t)(ibase + row) * N_TOK + jb2 + jq * 4);
            }
            CP_COMMIT();
        }

        int st3 = 0;
        for (int t = 0; t < NT_PER_CTA; ++t) {
            const int jb = jbase0 + t * JT;
            if (t >= 3) BAR_SYNC512(4 + st3);        /* P stage empty (t-3 done) */

            CP_WAIT2();                               /* own bias rows for tile t */
            __syncwarp();                             /* cross-lane visibility */

            /* prefetch bias tile t+3 (own rows; slot reuse is within-warp) */
            if (t + 3 < NT_PER_CTA) {
                const int slot = (t + 3) & 3;
                const int jb2 = jbase0 + (t + 3) * JT;
                const uint32_t dbase = sbase + BIAS_OFF + slot * BIAS_STG;
#pragma unroll
                for (int q = 0; q < 8; ++q) {
                    const int row = wid * 16 + q * 2 + rhalf;
                    CP_ASYNC16(dbase + row * 256 + jq * 16,
                               bias + (size_t)(ibase + row) * N_TOK + jb2 + jq * 4);
                }
            }
            CP_COMMIT();

            /* generate P rows w*16..w*16+15: 64 j -> f16 via ex2.f16x2 */
            char* ph = sm + PH_OFF + st3 * PSTG;
            const char* bslot = sm + BIAS_OFF + (t & 3) * BIAS_STG;
            const float4 f2v = *((const float4*)(g_f2 + jb) + jq);
#pragma unroll
            for (int k = 0; k < 8; ++k) {
                const int i = wid * 16 + k * 2 + rhalf;
                const float2 fc = fcl[i];
                const float4 bv = *(const float4*)(bslot + i * 256 + jq * 16);
                float x, t0, t1, t2, t3;
                x = fc.x + f2v.x; t0 = fmaxf(x, 0.2f * x);
                x = fc.x + f2v.y; t1 = fmaxf(x, 0.2f * x);
                x = fc.x + f2v.z; t2 = fmaxf(x, 0.2f * x);
                x = fc.x + f2v.w; t3 = fmaxf(x, 0.2f * x);
                const float g0 = fmaf(t0, LOG2E, fmaf(bv.x, LOG2E, fc.y));
                const float g1 = fmaf(t1, LOG2E, fmaf(bv.y, LOG2E, fc.y));
                const float g2 = fmaf(t2, LOG2E, fmaf(bv.z, LOG2E, fc.y));
                const float g3 = fmaf(t3, LOG2E, fmaf(bv.w, LOG2E, fc.y));
                *(uint2*)(ph + i * PSTRB + jq * 8) =
                    make_uint2(ex2h2(cvt2h(g0, g1)), ex2h2(cvt2h(g2, g3)));
            }
            BAR_ARRIVE512(1 + st3);                  /* signal P full */
            if (++st3 == 3) st3 = 0;
        }
    } else {
        /* ===================== CONSUMERS (256 thr) ===================== */
        const int cw   = wid - 8;                    /* 0..7 */
        const int rg   = cw & 3;                     /* row group: 32 rows  */
        const int cg2  = cw >> 2;                    /* col group: 32 cols  */
        const int ctid = tid - 256;                  /* 0..255 */
        float acc[2][4][4];
        float accO[2][4];
#pragma unroll
        for (int b = 0; b < 2; ++b) {
#pragma unroll
            for (int n = 0; n < 4; ++n)
#pragma unroll
                for (int q = 0; q < 4; ++q) acc[b][n][q] = 0.f;
#pragma unroll
            for (int q = 0; q < 4; ++q) accO[b][q] = 0.f;
        }

        const uint32_t rsel = (uint32_t)(lane & 15) * PSTRB + (uint32_t)(lane >> 4) * 16;
        const uint32_t vhb = sbase + VH_OFF;

        /* init ones block: V rows 64..79 (col 64 = 1.0, cols 65..79 = 0) */
        for (int u = ctid; u < 16 * 36; u += 256) {
            const int r = u / 36, w = u % 36;
            ((uint32_t*)(sm + VH_OFF + (64 + r) * PSTRB))[w] = (r == 0) ? 0x3C003C00u : 0u;
        }

        int st3 = 0;
        for (int t = 0; t < NT_PER_CTA; ++t) {
            const int jb = jbase0 + t * JT;

            /* issue V loads early (latency hides under the full-wait) */
            uint4 vh_r[2];
#pragma unroll
            for (int r = 0; r < 2; ++r) {
                const int u = r * 256 + ctid;
                const int c = u >> 3, q = u & 7;
                vh_r[r] = *((const uint4*)(g_ftsT + (size_t)c * N_TOK + jb) + q);
            }

            BAR_SYNC512(1 + st3);                    /* P full */

            /* stage V into (single) smem buffer */
#pragma unroll
            for (int r = 0; r < 2; ++r) {
                const int u = r * 256 + ctid;
                const int c = u >> 3, q = u & 7;
                *(uint4*)(sm + VH_OFF + c * PSTRB + q * 16) = vh_r[r];
            }
            BAR_SYNC256(8);                          /* V (+ones) visible */

            const uint32_t ph = sbase + PH_OFF + st3 * PSTG;

#pragma unroll
            for (int ks = 0; ks < 4; ++ks) {
                const uint32_t kofs = (uint32_t)ks * 32;   /* 16 f16 = 32B */
                uint32_t ah0[4], ah1[4];
                ldsm4(ah0[0], ah0[1], ah0[2], ah0[3],
                      ph + (rg * 32) * PSTRB + kofs + rsel);
                ldsm4(ah1[0], ah1[1], ah1[2], ah1[3],
                      ph + (rg * 32 + 16) * PSTRB + kofs + rsel);
                uint32_t b0[4], b1[4];
                ldsm4(b0[0], b0[1], b0[2], b0[3],
                      vhb + ((cg2 * 2) * 16) * PSTRB + kofs + rsel);
                ldsm4(b1[0], b1[1], b1[2], b1[3],
                      vhb + ((cg2 * 2 + 1) * 16) * PSTRB + kofs + rsel);
                mma16816(acc[0][0], ah0, b0[0], b0[2]);
                mma16816(acc[0][1], ah0, b0[1], b0[3]);
                mma16816(acc[0][2], ah0, b1[0], b1[2]);
                mma16816(acc[0][3], ah0, b1[1], b1[3]);
                mma16816(acc[1][0], ah1, b0[0], b0[2]);
                mma16816(acc[1][1], ah1, b0[1], b0[3]);
                mma16816(acc[1][2], ah1, b1[0], b1[2]);
                mma16816(acc[1][3], ah1, b1[1], b1[3]);
                if (cg2 == 1) {                      /* ones block: row sums */
                    uint32_t bo[4];
                    ldsm4(bo[0], bo[1], bo[2], bo[3],
                          vhb + 64 * PSTRB + kofs + rsel);
                    mma16816(accO[0], ah0, bo[0], bo[2]);
                    mma16816(accO[1], ah1, bo[0], bo[2]);
                }
            }
            BAR_ARRIVE512(4 + st3);                  /* signal P empty */
            if (++st3 == 3) st3 = 0;
        }

        /* write partials (rows rg*32.., cols cg2*32..) + denominators */
#pragma unroll
        for (int b = 0; b < 2; ++b) {
            const int m = rg * 32 + b * 16 + (lane >> 2);
            float* dst0 = g_acc + ((size_t)s * N_TOK + ibase + m) * OUTD;
            float* dst8 = dst0 + 8 * OUTD;
#pragma unroll
            for (int n = 0; n < 4; ++n) {
                const int c = cg2 * 32 + n * 8 + (lane & 3) * 2;
                *(float2*)(dst0 + c) = make_float2(acc[b][n][0], acc[b][n][1]);
                *(float2*)(dst8 + c) = make_float2(acc[b][n][2], acc[b][n][3]);
            }
            if (cg2 == 1 && (lane & 3) == 0) {
                g_den[(size_t)s * N_TOK + ibase + m]     = accO[b][0];
                g_den[(size_t)s * N_TOK + ibase + m + 8] = accO[b][2];
            }
        }
    }
}

/* ------------------------------------------------------------------ */
__global__ __launch_bounds__(256) void k4_combine(float* __restrict__ out) {
    const int idx = blockIdx.x * 256 + threadIdx.x;
    if (blockIdx.x == 0 && threadIdx.x == 0) g_f2maxu = 0u;  /* reset for next replay */
    if (idx >= N_TOK * 16) return;
    const int i = idx >> 4;
    float den = 0.f;
    float4 a = make_float4(0.f, 0.f, 0.f, 0.f);
#pragma unroll
    for (int s = 0; s < NSPLIT; ++s) {
        den += g_den[s * N_TOK + i];
        const float4 p = ((const float4*)g_acc)[(size_t)s * N_TOK * 16 + idx];
        a.x += p.x; a.y += p.y; a.z += p.z; a.w += p.w;
    }
    const float inv = 1.f / den;
    float4 r = make_float4(a.x * inv, a.y * inv, a.z * inv, a.w * inv);
    r.x = r.x > 0.f ? r.x : expm1f(r.x);
    r.y = r.y > 0.f ? r.y : expm1f(r.y);
    r.z = r.z > 0.f ? r.z : expm1f(r.z);
    r.w = r.w > 0.f ? r.w : expm1f(r.w);
    ((float4*)out)[idx] = r;
}

/* ------------------------------------------------------------------ */
extern "C" void kernel_launch(void* const* d_in, const int* in_sizes, int n_in,
                              void* d_out, int out_size) {
    const float* seq  = (const float*)d_in[0];
    const float* bias = (const float*)d_in[1];
    const float* W1   = (const float*)d_in[2];
    const float* a1   = (const float*)d_in[3];
    const float* b1   = (const float*)d_in[4];
    const float* a2   = (const float*)d_in[5];
    const float* b2   = (const float*)d_in[6];
    float* out = (float*)d_out;

    cudaFuncSetAttribute(k1_fts,  cudaFuncAttributeMaxDynamicSharedMemorySize, SMEM1_BYTES);
    cudaFuncSetAttribute(k3_attn, cudaFuncAttributeMaxDynamicSharedMemorySize, SMEM3_BYTES);

    k1_fts<<<128, 512, SMEM1_BYTES>>>(seq, W1, a1, b1, a2, b2);
    dim3 g3(N_TOK / M_TILE, NSPLIT);
    k3_attn<<<g3, 512, SMEM3_BYTES>>>(bias);
    k4_combine<<<(N_TOK * 16) / 256, 256>>>(out);
}